// round 2
// baseline (speedup 1.0000x reference)
#include <cuda_runtime.h>

#define BN       16384
#define NLOC     12
#define FDIM     512
#define HDIM     256
#define RROWS    16
#define NTHREADS 512
#define NWARPS   (NTHREADS/32)

// dynamic smem layout (floats):
//  sg[R*F] | sgq[R*H] (later ltg) | sgv[R*H] (later wg) | su[R*F] (later stage)
//  sp[R*F] | slfm[R*F] | sred[NWARPS*NLOC] | sa2[NLOC] | swdr[NLOC] | smisc[2]
#define SMEM_FLOATS (RROWS*FDIM + RROWS*HDIM + RROWS*HDIM + RROWS*FDIM + \
                     RROWS*FDIM + RROWS*FDIM + NWARPS*NLOC + NLOC + NLOC + 8)
#define SMEM_BYTES  (SMEM_FLOATS * 4)

__global__ __launch_bounds__(NTHREADS, 1)
void esf_fused(const float* __restrict__ g,     // [B,F]
               const float* __restrict__ lf,    // [B,NLOC,F]
               const float* __restrict__ Wq, const float* __restrict__ bq,
               const float* __restrict__ Wk,
               const float* __restrict__ Wv, const float* __restrict__ bv,
               const float* __restrict__ w_dr, const float* __restrict__ b_dr,
               const float* __restrict__ Wf, const float* __restrict__ bf,
               float* __restrict__ out)         // [B,F]
{
    extern __shared__ float sm[];
    float* sg    = sm;                          // RROWS*FDIM
    float* sgq   = sg    + RROWS*FDIM;          // RROWS*HDIM  (reused for ltg)
    float* sgv   = sgq   + RROWS*HDIM;          // RROWS*HDIM  (reused for wg)
    float* su    = sgv   + RROWS*HDIM;          // RROWS*FDIM  (reused as stage)
    float* sp    = su    + RROWS*FDIM;          // RROWS*FDIM
    float* slfm  = sp    + RROWS*FDIM;          // RROWS*FDIM
    float* sred  = slfm  + RROWS*FDIM;          // NWARPS*NLOC
    float* sa2   = sred  + NWARPS*NLOC;         // NLOC
    float* swdr  = sa2   + NLOC;                // NLOC
    float* smisc = swdr  + NLOC;                // [0]=Sw, [1]=b_dr

    const int tid  = threadIdx.x;
    const int lane = tid & 31;
    const int wid  = tid >> 5;
    const size_t row0 = (size_t)blockIdx.x * RROWS;

    if (tid == 0) {
        float s = 0.f;
        for (int k = 0; k < NLOC; ++k) { float w = w_dr[k]; swdr[k] = w; s += w; }
        smisc[0] = s;
        smisc[1] = b_dr[0];
    }
    // stage the 16 global-feature rows
    for (int i = tid; i < RROWS*FDIM; i += NTHREADS)
        sg[i] = g[row0*FDIM + i];
    __syncthreads();

    // ---- step 1: gq (threads 0..255) and gv (threads 256..511), batched over R rows ----
    {
        const int  h   = tid & (HDIM-1);
        const bool isQ = tid < HDIM;
        const float* W = isQ ? Wq : Wv;
        const float bias = (isQ ? bq : bv)[h];
        float acc[RROWS];
        #pragma unroll
        for (int r = 0; r < RROWS; ++r) acc[r] = bias;
        #pragma unroll 4
        for (int f = 0; f < FDIM; ++f) {
            float w = W[f*HDIM + h];
            #pragma unroll
            for (int r = 0; r < RROWS; ++r) acc[r] = fmaf(sg[r*FDIM + f], w, acc[r]);
        }
        float* dst = isQ ? sgq : sgv;
        #pragma unroll
        for (int r = 0; r < RROWS; ++r) dst[r*HDIM + h] = acc[r];
    }
    __syncthreads();

    // ---- step 2: u[r][f] = Wk[f,:]·gq[r,:]  (warp per f, warp reduce) ----
    for (int f = wid; f < FDIM; f += NWARPS) {
        float acc[RROWS];
        #pragma unroll
        for (int r = 0; r < RROWS; ++r) acc[r] = 0.f;
        #pragma unroll
        for (int j = 0; j < HDIM/32; ++j) {
            int h = lane + j*32;
            float w = Wk[f*HDIM + h];
            #pragma unroll
            for (int r = 0; r < RROWS; ++r) acc[r] = fmaf(w, sgq[r*HDIM + h], acc[r]);
        }
        #pragma unroll
        for (int r = 0; r < RROWS; ++r) {
            #pragma unroll
            for (int off = 16; off > 0; off >>= 1)
                acc[r] += __shfl_xor_sync(0xffffffffu, acc[r], off);
        }
        if (lane == 0) {
            #pragma unroll
            for (int r = 0; r < RROWS; ++r) su[r*FDIM + f] = acc[r];
        }
    }
    __syncthreads();

    // ---- steps 3-5 per row: s2 = scale·(lf·u), softmax(12), p = Σ a2·lf, lf_mean ----
    const float scale = 1.0f / 16.0f;   // 1/sqrt(256)
    for (int r = 0; r < RROWS; ++r) {
        const float* lfrow = lf + (row0 + r) * (size_t)(NLOC*FDIM);
        float lfv[NLOC], part[NLOC];
        const float uf = su[r*FDIM + tid];
        #pragma unroll
        for (int k = 0; k < NLOC; ++k) lfv[k] = lfrow[k*FDIM + tid];
        #pragma unroll
        for (int k = 0; k < NLOC; ++k) part[k] = lfv[k] * uf;
        #pragma unroll
        for (int k = 0; k < NLOC; ++k) {
            #pragma unroll
            for (int off = 16; off > 0; off >>= 1)
                part[k] += __shfl_xor_sync(0xffffffffu, part[k], off);
        }
        if (lane == 0) {
            #pragma unroll
            for (int k = 0; k < NLOC; ++k) sred[wid*NLOC + k] = part[k];
        }
        __syncthreads();
        if (tid == 0) {
            float s2[NLOC];
            for (int k = 0; k < NLOC; ++k) {
                float a = 0.f;
                for (int w = 0; w < NWARPS; ++w) a += sred[w*NLOC + k];
                s2[k] = a * scale;
            }
            float m = s2[0];
            for (int k = 1; k < NLOC; ++k) m = fmaxf(m, s2[k]);
            float se = 0.f;
            for (int k = 0; k < NLOC; ++k) { s2[k] = expf(s2[k] - m); se += s2[k]; }
            float inv = 1.f / se;
            for (int k = 0; k < NLOC; ++k) sa2[k] = s2[k] * inv;
        }
        __syncthreads();
        float p = 0.f, lm = 0.f;
        #pragma unroll
        for (int k = 0; k < NLOC; ++k) {
            p  = fmaf(sa2[k],  lfv[k], p);
            lm = fmaf(swdr[k], lfv[k], lm);
        }
        sp[r*FDIM + tid]   = p;
        slfm[r*FDIM + tid] = lm + smisc[1];
    }
    __syncthreads();

    // ---- step 6: ltg[r][h] = bv[h] + Σ_f p[r][f]·Wv[f,h]  (two f-halves) ----
    {
        const int h    = tid & (HDIM-1);
        const int half = tid >> 8;
        float acc[RROWS];
        #pragma unroll
        for (int r = 0; r < RROWS; ++r) acc[r] = 0.f;
        const int f0 = half * (FDIM/2);
        #pragma unroll 4
        for (int f = f0; f < f0 + FDIM/2; ++f) {
            float w = Wv[f*HDIM + h];
            #pragma unroll
            for (int r = 0; r < RROWS; ++r) acc[r] = fmaf(sp[r*FDIM + f], w, acc[r]);
        }
        if (half == 1) {
            #pragma unroll
            for (int r = 0; r < RROWS; ++r) su[r*HDIM + h] = acc[r];   // stage upper half
        }
        __syncthreads();
        if (half == 0) {
            const float bias = bv[h];
            #pragma unroll
            for (int r = 0; r < RROWS; ++r)
                sgq[r*HDIM + h] = acc[r] + su[r*HDIM + h] + bias;      // ltg overwrites gq
        }
    }
    __syncthreads();
    // fold wg = gv·Sw + b_dr in place
    {
        const float Sw  = smisc[0];
        const float bdr = smisc[1];
        for (int i = tid; i < RROWS*HDIM; i += NTHREADS)
            sgv[i] = fmaf(sgv[i], Sw, bdr);
    }
    __syncthreads();

    // ---- step 7: out = relu([ltg, wg] @ Wf + bf) + lf_mean + g ----
    {
        const int fo = tid;
        float acc[RROWS];
        const float bfo = bf[fo];
        #pragma unroll
        for (int r = 0; r < RROWS; ++r) acc[r] = bfo;
        #pragma unroll 2
        for (int j = 0; j < HDIM; ++j) {
            float w = Wf[j*FDIM + fo];
            #pragma unroll
            for (int r = 0; r < RROWS; ++r) acc[r] = fmaf(sgq[r*HDIM + j], w, acc[r]);
        }
        #pragma unroll 2
        for (int j = 0; j < HDIM; ++j) {
            float w = Wf[(HDIM + j)*FDIM + fo];
            #pragma unroll
            for (int r = 0; r < RROWS; ++r) acc[r] = fmaf(sgv[r*HDIM + j], w, acc[r]);
        }
        #pragma unroll
        for (int r = 0; r < RROWS; ++r) {
            float v = fmaxf(acc[r], 0.f) + slfm[r*FDIM + fo] + sg[r*FDIM + fo];
            out[(row0 + r)*FDIM + fo] = v;
        }
    }
}

extern "C" void kernel_launch(void* const* d_in, const int* in_sizes, int n_in,
                              void* d_out, int out_size)
{
    const float* g    = (const float*)d_in[0];
    const float* lf   = (const float*)d_in[1];
    const float* Wq   = (const float*)d_in[2];
    const float* bq   = (const float*)d_in[3];
    const float* Wk   = (const float*)d_in[4];
    // d_in[5] = bk: provably unused (constant shift cancels in softmax)
    const float* Wv   = (const float*)d_in[6];
    const float* bv   = (const float*)d_in[7];
    const float* w_dr = (const float*)d_in[8];
    const float* b_dr = (const float*)d_in[9];
    const float* Wf   = (const float*)d_in[10];
    const float* bf   = (const float*)d_in[11];
    float* out = (float*)d_out;

    cudaFuncSetAttribute(esf_fused, cudaFuncAttributeMaxDynamicSharedMemorySize, SMEM_BYTES);
    esf_fused<<<BN / RROWS, NTHREADS, SMEM_BYTES>>>(
        g, lf, Wq, bq, Wk, Wv, bv, w_dr, b_dr, Wf, bf, out);
}

// round 7
// speedup vs baseline: 1.7783x; 1.7783x over previous
#include <cuda_runtime.h>
#include <cstdint>
#include <cstddef>

#define B_N   16384
#define F_D   512
#define H_D   256
#define NLOC  12

// ---------------- device scratch (no allocations allowed) ----------------
__device__ float DU  [B_N * F_D];       // u = g@M1 + c_u
__device__ float DP  [B_N * F_D];       // p = softmax-weighted lf
__device__ float DLFM[B_N * F_D];       // lf_mean + b_dr
__device__ float DM1 [F_D * F_D];       // Wq @ Wk^T
__device__ float DW2 [2 * F_D * F_D];   // rows 0..511: Sw*(Wv@Wf_bot) (mult g); 512..1023: Wv@Wf_top (mult p)
__device__ float DCU [F_D];
__device__ float DCZ [F_D];
__device__ float DSWB[2];               // [0]=sum(w_dr), [1]=b_dr

// ---------------- tiny helpers ----------------
__device__ __forceinline__ unsigned long long pk2(float lo, float hi) {
    unsigned long long r;
    asm("mov.b64 %0, {%1,%2};" : "=l"(r) : "f"(lo), "f"(hi));
    return r;
}
__device__ __forceinline__ void fma2(unsigned long long& c, unsigned long long a, unsigned long long b) {
    asm("fma.rn.f32x2 %0, %1, %2, %0;" : "+l"(c) : "l"(a), "l"(b));
}
__device__ __forceinline__ float upk_sum(unsigned long long v) {
    float lo, hi;
    asm("mov.b64 {%0,%1}, %2;" : "=f"(lo), "=f"(hi) : "l"(v));
    return lo + hi;
}
__device__ __forceinline__ void cpa16(unsigned int s, const void* g) {
    asm volatile("cp.async.cg.shared.global [%0], [%1], 16;\n" :: "r"(s), "l"(g));
}
__device__ __forceinline__ void cpa_commit() { asm volatile("cp.async.commit_group;\n"); }
__device__ __forceinline__ void cpa_wait0()  { asm volatile("cp.async.wait_group 0;\n"); }

// ---------------- kernel 0: scalars ----------------
__global__ void k_sw(const float* __restrict__ w_dr, const float* __restrict__ b_dr) {
    if (threadIdx.x == 0) {
        float s = 0.f;
        for (int k = 0; k < NLOC; ++k) s += w_dr[k];
        DSWB[0] = s;
        DSWB[1] = b_dr[0];
    }
}

// ---------------- kernel 1: weight prep (3 small 512x512x256 GEMMs) ----------------
// mat 0: DM1[m][n]        = sum_h Wq[m][h] * Wk[n][h]
// mat 1: DW2[m][n]        = Sw * sum_h Wv[m][h] * Wf[256+h][n]
// mat 2: DW2[512+m][n]    =      sum_h Wv[m][h] * Wf[h][n]
__global__ __launch_bounds__(256) void k_prep(const float* __restrict__ Wq,
                                              const float* __restrict__ Wk,
                                              const float* __restrict__ Wv,
                                              const float* __restrict__ Wf) {
    __shared__ float As[16][68];
    __shared__ float Bs[16][68];
    const int tid = threadIdx.x;
    const int tx = tid & 15, ty = tid >> 4;
    const int m0 = blockIdx.y * 64, n0 = blockIdx.x * 64, mat = blockIdx.z;
    const float* A = (mat == 0) ? Wq : Wv;
    float acc[4][4];
    #pragma unroll
    for (int i = 0; i < 4; ++i)
        #pragma unroll
        for (int j = 0; j < 4; ++j) acc[i][j] = 0.f;

    for (int kk = 0; kk < 256; kk += 16) {
        {   // A: rows m0..m0+63, k chunk; store transposed As[k][m]
            int m = tid >> 2, kq = (tid & 3) * 4;
            float4 v = *(const float4*)&A[(m0 + m) * 256 + kk + kq];
            As[kq + 0][m] = v.x; As[kq + 1][m] = v.y; As[kq + 2][m] = v.z; As[kq + 3][m] = v.w;
        }
        if (mat == 0) {  // B[k][n] = Wk[n][k] (transpose on store)
            int n = tid >> 2, kq = (tid & 3) * 4;
            float4 v = *(const float4*)&Wk[(n0 + n) * 256 + kk + kq];
            Bs[kq + 0][n] = v.x; Bs[kq + 1][n] = v.y; Bs[kq + 2][n] = v.z; Bs[kq + 3][n] = v.w;
        } else {         // B[k][n] = Wf[off+k][n] (natural rows)
            int kr = tid >> 4, nq = (tid & 15) * 4;
            int off = (mat == 1) ? 256 : 0;
            float4 v = *(const float4*)&Wf[(off + kk + kr) * 512 + n0 + nq];
            *(float4*)&Bs[kr][nq] = v;
        }
        __syncthreads();
        #pragma unroll
        for (int k = 0; k < 16; ++k) {
            float4 a = *(const float4*)&As[k][ty * 4];
            float4 b = *(const float4*)&Bs[k][tx * 4];
            float av[4] = {a.x, a.y, a.z, a.w};
            float bv[4] = {b.x, b.y, b.z, b.w};
            #pragma unroll
            for (int i = 0; i < 4; ++i)
                #pragma unroll
                for (int j = 0; j < 4; ++j) acc[i][j] = fmaf(av[i], bv[j], acc[i][j]);
        }
        __syncthreads();
    }
    const float sw = DSWB[0];
    #pragma unroll
    for (int i = 0; i < 4; ++i) {
        int m = m0 + ty * 4 + i;
        #pragma unroll
        for (int j = 0; j < 4; ++j) {
            int n = n0 + tx * 4 + j;
            if (mat == 0)      DM1[m * 512 + n]        = acc[i][j];
            else if (mat == 1) DW2[m * 512 + n]        = acc[i][j] * sw;
            else               DW2[(512 + m) * 512 + n] = acc[i][j];
        }
    }
}

// ---------------- kernel 2: constant vectors ----------------
__global__ void k_const(const float* __restrict__ bq, const float* __restrict__ Wk,
                        const float* __restrict__ bv, const float* __restrict__ Wf,
                        const float* __restrict__ bf) {
    const int o = threadIdx.x;   // 512 threads
    const float sw = DSWB[0], bdr = DSWB[1];
    float cu = 0.f;
    for (int h = 0; h < 256; ++h) cu = fmaf(bq[h], Wk[o * 256 + h], cu);
    DCU[o] = cu;
    float cz = bf[o];
    for (int h = 0; h < 256; ++h) {
        cz = fmaf(bv[h], Wf[h * 512 + o], cz);
        cz = fmaf(fmaf(sw, bv[h], bdr), Wf[(256 + h) * 512 + o], cz);
    }
    DCZ[o] = cz;
}

// ---------------- main GEMM: [B x K] @ [K x 512], f32x2 packed, k-pair acc ----------------
// KTOT 512: B = DM1;  KTOT 1024: B = DW2, A = [g | DP]
// MODE 0: DU = acc + DCU;   MODE 1: out = relu(acc + DCZ) + DLFM + g
#define ASTR 20
template<int KTOT, int MODE>
__global__ __launch_bounds__(256, 2) void k_gemm(const float* __restrict__ G,
                                                 float* __restrict__ Out) {
    __shared__ float As[2][128 * ASTR];
    __shared__ float Bs[2][16 * 64];
    const int tid = threadIdx.x;
    const int tx = tid & 15, ty = tid >> 4;
    const int row0 = blockIdx.y * 128;
    const int n0   = blockIdx.x * 64;
    const float* Bw = (KTOT == 512) ? DM1 : DW2;

    unsigned long long acc[8][4];
    #pragma unroll
    for (int i = 0; i < 8; ++i)
        #pragma unroll
        for (int j = 0; j < 4; ++j) acc[i][j] = 0ULL;

    const int m_a  = tid >> 1, kq_a = (tid & 1) * 8;
    const int kr_b = tid >> 4, nq_b = (tid & 15) * 4;

    auto load_chunk = [&](int buf, int kk) {
        const float* Asrc = G; int kloc = kk;
        if (KTOT == 1024 && kk >= 512) { Asrc = DP; kloc = kk - 512; }
        const float* ga = &Asrc[(size_t)(row0 + m_a) * 512 + kloc + kq_a];
        unsigned int sa = (unsigned int)__cvta_generic_to_shared(&As[buf][m_a * ASTR + kq_a]);
        cpa16(sa, ga);
        cpa16(sa + 16, ga + 4);
        const float* gb = &Bw[(size_t)(kk + kr_b) * 512 + n0 + nq_b];
        unsigned int sb = (unsigned int)__cvta_generic_to_shared(&Bs[buf][kr_b * 64 + nq_b]);
        cpa16(sb, gb);
        cpa_commit();
    };

    load_chunk(0, 0);
    cpa_wait0();
    __syncthreads();

    const int NC = KTOT / 16;
    for (int c = 0; c < NC; ++c) {
        if (c + 1 < NC) load_chunk((c + 1) & 1, (c + 1) * 16);
        const float* As_ = As[c & 1];
        const float* Bs_ = Bs[c & 1];
        #pragma unroll
        for (int kp = 0; kp < 8; ++kp) {
            unsigned long long av[8];
            #pragma unroll
            for (int i = 0; i < 8; ++i)
                av[i] = *(const unsigned long long*)&As_[(ty * 8 + i) * ASTR + 2 * kp];
            float4 b0 = *(const float4*)&Bs_[(2 * kp) * 64 + tx * 4];
            float4 b1 = *(const float4*)&Bs_[(2 * kp + 1) * 64 + tx * 4];
            unsigned long long bp[4];
            bp[0] = pk2(b0.x, b1.x); bp[1] = pk2(b0.y, b1.y);
            bp[2] = pk2(b0.z, b1.z); bp[3] = pk2(b0.w, b1.w);
            #pragma unroll
            for (int i = 0; i < 8; ++i)
                #pragma unroll
                for (int j = 0; j < 4; ++j) fma2(acc[i][j], av[i], bp[j]);
        }
        cpa_wait0();
        __syncthreads();
    }

    #pragma unroll
    for (int i = 0; i < 8; ++i) {
        const int m = row0 + ty * 8 + i;
        const int n = n0 + tx * 4;
        float v0 = upk_sum(acc[i][0]);
        float v1 = upk_sum(acc[i][1]);
        float v2 = upk_sum(acc[i][2]);
        float v3 = upk_sum(acc[i][3]);
        float4 o;
        if (MODE == 0) {
            o.x = v0 + DCU[n + 0]; o.y = v1 + DCU[n + 1];
            o.z = v2 + DCU[n + 2]; o.w = v3 + DCU[n + 3];
            *(float4*)&DU[(size_t)m * 512 + n] = o;
        } else {
            float4 lm = *(const float4*)&DLFM[(size_t)m * 512 + n];
            float4 g4 = *(const float4*)&G[(size_t)m * 512 + n];
            o.x = fmaxf(v0 + DCZ[n + 0], 0.f) + lm.x + g4.x;
            o.y = fmaxf(v1 + DCZ[n + 1], 0.f) + lm.y + g4.y;
            o.z = fmaxf(v2 + DCZ[n + 2], 0.f) + lm.z + g4.z;
            o.w = fmaxf(v3 + DCZ[n + 3], 0.f) + lm.w + g4.w;
            *(float4*)&Out[(size_t)m * 512 + n] = o;
        }
    }
}

// ---------------- middle kernel: softmax over 12 local tokens ----------------
__global__ __launch_bounds__(128) void k_mid(const float* __restrict__ lf,
                                             const float* __restrict__ w_dr) {
    __shared__ float sred[4][NLOC];
    __shared__ float swd[NLOC];
    const int b = blockIdx.x, tid = threadIdx.x;
    const int lane = tid & 31, w = tid >> 5;
    if (tid < NLOC) swd[tid] = w_dr[tid];

    float4 u4 = *(const float4*)&DU[(size_t)b * 512 + tid * 4];
    const float* base = lf + (size_t)b * NLOC * 512 + tid * 4;
    float4 lfv[NLOC];
    float part[NLOC];
    #pragma unroll
    for (int k = 0; k < NLOC; ++k) {
        lfv[k] = *(const float4*)&base[k * 512];
        part[k] = lfv[k].x * u4.x + lfv[k].y * u4.y + lfv[k].z * u4.z + lfv[k].w * u4.w;
    }
    #pragma unroll
    for (int k = 0; k < NLOC; ++k) {
        #pragma unroll
        for (int off = 16; off > 0; off >>= 1)
            part[k] += __shfl_xor_sync(0xffffffffu, part[k], off);
    }
    if (lane == 0) {
        #pragma unroll
        for (int k = 0; k < NLOC; ++k) sred[w][k] = part[k];
    }
    __syncthreads();

    float a2[NLOC], mx = -1e30f;
    #pragma unroll
    for (int k = 0; k < NLOC; ++k) {
        float s = (sred[0][k] + sred[1][k] + sred[2][k] + sred[3][k]) * 0.0625f;  // 1/sqrt(256)
        a2[k] = s;
        mx = fmaxf(mx, s);
    }
    float se = 0.f;
    #pragma unroll
    for (int k = 0; k < NLOC; ++k) { a2[k] = expf(a2[k] - mx); se += a2[k]; }
    const float inv = 1.f / se;
    const float bdr = DSWB[1];

    float4 p = {0, 0, 0, 0}, lm = {0, 0, 0, 0};
    #pragma unroll
    for (int k = 0; k < NLOC; ++k) {
        float ak = a2[k] * inv, wk = swd[k];
        p.x = fmaf(ak, lfv[k].x, p.x);  p.y = fmaf(ak, lfv[k].y, p.y);
        p.z = fmaf(ak, lfv[k].z, p.z);  p.w = fmaf(ak, lfv[k].w, p.w);
        lm.x = fmaf(wk, lfv[k].x, lm.x); lm.y = fmaf(wk, lfv[k].y, lm.y);
        lm.z = fmaf(wk, lfv[k].z, lm.z); lm.w = fmaf(wk, lfv[k].w, lm.w);
    }
    lm.x += bdr; lm.y += bdr; lm.z += bdr; lm.w += bdr;
    *(float4*)&DP  [(size_t)b * 512 + tid * 4] = p;
    *(float4*)&DLFM[(size_t)b * 512 + tid * 4] = lm;
}

// ---------------- launch ----------------
extern "C" void kernel_launch(void* const* d_in, const int* in_sizes, int n_in,
                              void* d_out, int out_size) {
    const float* g    = (const float*)d_in[0];
    const float* lf   = (const float*)d_in[1];
    const float* Wq   = (const float*)d_in[2];
    const float* bq   = (const float*)d_in[3];
    const float* Wk   = (const float*)d_in[4];
    // d_in[5] = bk: cancels in the softmax — unused
    const float* Wv   = (const float*)d_in[6];
    const float* bv   = (const float*)d_in[7];
    const float* w_dr = (const float*)d_in[8];
    const float* b_dr = (const float*)d_in[9];
    const float* Wf   = (const float*)d_in[10];
    const float* bf   = (const float*)d_in[11];
    float* out = (float*)d_out;

    k_sw<<<1, 32>>>(w_dr, b_dr);
    k_prep<<<dim3(8, 8, 3), 256>>>(Wq, Wk, Wv, Wf);
    k_const<<<1, 512>>>(bq, Wk, bv, Wf, bf);
    k_gemm<512, 0><<<dim3(8, 128), 256>>>(g, nullptr);   // U = g@M1 + c_u
    k_mid<<<B_N, 128>>>(lf, w_dr);                       // softmax / p / lfm
    k_gemm<1024, 1><<<dim3(8, 128), 256>>>(g, out);      // out = relu([g|p]@W2 + c_z) + lfm + g
}

// round 10
// speedup vs baseline: 3.3167x; 1.8651x over previous
#include <cuda_runtime.h>
#include <cuda_bf16.h>
#include <cstdint>
#include <cstddef>

#define B_N   16384
#define F_D   512
#define H_D   256
#define NLOC  12

// ---------------- device scratch ----------------
__device__ float         DU  [B_N * F_D];        // u = g@M1 + c_u (fp32, for k_mid)
__device__ float         DLFM[B_N * F_D];        // lf_mean + b_dr
__device__ __nv_bfloat16 GH[B_N * F_D], GL[B_N * F_D];    // g split
__device__ __nv_bfloat16 DPH[B_N * F_D], DPL[B_N * F_D];  // p split
__device__ __nv_bfloat16 M1TH[F_D * F_D], M1TL[F_D * F_D];        // (Wq@Wk^T)^T : [n][k]
__device__ __nv_bfloat16 W2TH[F_D * 2 * F_D], W2TL[F_D * 2 * F_D];// W2^T : [n][k]
__device__ float DCU [F_D];
__device__ float DCZ [F_D];
__device__ float DSWB[2];                        // [0]=sum(w_dr), [1]=b_dr

// ---------------- PTX helpers ----------------
__device__ __forceinline__ void cpa16(unsigned int s, const void* g) {
    asm volatile("cp.async.cg.shared.global [%0], [%1], 16;\n" :: "r"(s), "l"(g));
}
__device__ __forceinline__ void cpa_commit() { asm volatile("cp.async.commit_group;\n"); }
__device__ __forceinline__ void cpa_wait0()  { asm volatile("cp.async.wait_group 0;\n"); }
__device__ __forceinline__ void cpa_wait1()  { asm volatile("cp.async.wait_group 1;\n"); }

__device__ __forceinline__ void mma_bf16(float* c, uint32_t a0, uint32_t a1, uint32_t a2,
                                         uint32_t a3, uint32_t b0, uint32_t b1) {
    asm volatile(
        "mma.sync.aligned.m16n8k16.row.col.f32.bf16.bf16.f32 "
        "{%0,%1,%2,%3}, {%4,%5,%6,%7}, {%8,%9}, {%0,%1,%2,%3};\n"
        : "+f"(c[0]), "+f"(c[1]), "+f"(c[2]), "+f"(c[3])
        : "r"(a0), "r"(a1), "r"(a2), "r"(a3), "r"(b0), "r"(b1));
}

__device__ __forceinline__ void split_bf16(float x, __nv_bfloat16& h, __nv_bfloat16& l) {
    h = __float2bfloat16(x);
    l = __float2bfloat16(x - __bfloat162float(h));
}

// ---------------- kernel 0: scalars ----------------
__global__ void k_sw(const float* __restrict__ w_dr, const float* __restrict__ b_dr) {
    if (threadIdx.x == 0) {
        float s = 0.f;
        for (int k = 0; k < NLOC; ++k) s += w_dr[k];
        DSWB[0] = s;
        DSWB[1] = b_dr[0];
    }
}

// ---------------- kernel 1: weight prep -> transposed bf16 hi/lo ----------------
// mat 0: M1T[n][k]        = sum_h Wq[k][h] * Wk[n][h]
// mat 1: W2T[n][k], k<512 = Sw * sum_h Wv[k][h] * Wf[256+h][n]   (multiplies g)
// mat 2: W2T[n][512+k]    =      sum_h Wv[k][h] * Wf[h][n]       (multiplies p)
__global__ __launch_bounds__(256) void k_prep(const float* __restrict__ Wq,
                                              const float* __restrict__ Wk,
                                              const float* __restrict__ Wv,
                                              const float* __restrict__ Wf) {
    __shared__ float As[16][68];
    __shared__ float Bs[16][68];
    const int tid = threadIdx.x;
    const int tx = tid & 15, ty = tid >> 4;
    const int m0 = blockIdx.y * 64, n0 = blockIdx.x * 64, mat = blockIdx.z;
    const float* A = (mat == 0) ? Wq : Wv;
    float acc[4][4];
    #pragma unroll
    for (int i = 0; i < 4; ++i)
        #pragma unroll
        for (int j = 0; j < 4; ++j) acc[i][j] = 0.f;

    for (int kk = 0; kk < 256; kk += 16) {
        {
            int m = tid >> 2, kq = (tid & 3) * 4;
            float4 v = *(const float4*)&A[(m0 + m) * 256 + kk + kq];
            As[kq + 0][m] = v.x; As[kq + 1][m] = v.y; As[kq + 2][m] = v.z; As[kq + 3][m] = v.w;
        }
        if (mat == 0) {
            int n = tid >> 2, kq = (tid & 3) * 4;
            float4 v = *(const float4*)&Wk[(n0 + n) * 256 + kk + kq];
            Bs[kq + 0][n] = v.x; Bs[kq + 1][n] = v.y; Bs[kq + 2][n] = v.z; Bs[kq + 3][n] = v.w;
        } else {
            int kr = tid >> 4, nq = (tid & 15) * 4;
            int off = (mat == 1) ? 256 : 0;
            float4 v = *(const float4*)&Wf[(off + kk + kr) * 512 + n0 + nq];
            *(float4*)&Bs[kr][nq] = v;
        }
        __syncthreads();
        #pragma unroll
        for (int k = 0; k < 16; ++k) {
            float4 a = *(const float4*)&As[k][ty * 4];
            float4 b = *(const float4*)&Bs[k][tx * 4];
            float av[4] = {a.x, a.y, a.z, a.w};
            float bv[4] = {b.x, b.y, b.z, b.w};
            #pragma unroll
            for (int i = 0; i < 4; ++i)
                #pragma unroll
                for (int j = 0; j < 4; ++j) acc[i][j] = fmaf(av[i], bv[j], acc[i][j]);
        }
        __syncthreads();
    }
    const float sw = DSWB[0];
    #pragma unroll
    for (int i = 0; i < 4; ++i) {
        int m = m0 + ty * 4 + i;            // k index of the big GEMM
        #pragma unroll
        for (int j = 0; j < 4; ++j) {
            int n = n0 + tx * 4 + j;        // output col
            float v = acc[i][j];
            __nv_bfloat16 h, l;
            if (mat == 0) {
                split_bf16(v, h, l);
                M1TH[n * 512 + m] = h; M1TL[n * 512 + m] = l;
            } else if (mat == 1) {
                split_bf16(v * sw, h, l);
                W2TH[n * 1024 + m] = h; W2TL[n * 1024 + m] = l;
            } else {
                split_bf16(v, h, l);
                W2TH[n * 1024 + 512 + m] = h; W2TL[n * 1024 + 512 + m] = l;
            }
        }
    }
}

// ---------------- kernel 2: constant vectors ----------------
__global__ void k_const(const float* __restrict__ bq, const float* __restrict__ Wk,
                        const float* __restrict__ bv, const float* __restrict__ Wf,
                        const float* __restrict__ bf) {
    const int o = threadIdx.x;   // 512 threads
    const float sw = DSWB[0], bdr = DSWB[1];
    float cu = 0.f;
    for (int h = 0; h < 256; ++h) cu = fmaf(bq[h], Wk[o * 256 + h], cu);
    DCU[o] = cu;
    float cz = bf[o];
    for (int h = 0; h < 256; ++h) {
        cz = fmaf(bv[h], Wf[h * 512 + o], cz);
        cz = fmaf(fmaf(sw, bv[h], bdr), Wf[(256 + h) * 512 + o], cz);
    }
    DCZ[o] = cz;
}

// ---------------- kernel 3: split g -> bf16 hi/lo ----------------
__global__ __launch_bounds__(256) void k_cvt_g(const float* __restrict__ g) {
    const size_t i = (size_t)blockIdx.x * 256 + threadIdx.x;   // float4 index
    float4 v = *(const float4*)&g[i * 4];
    __nv_bfloat16 h0, l0, h1, l1, h2, l2, h3, l3;
    split_bf16(v.x, h0, l0); split_bf16(v.y, h1, l1);
    split_bf16(v.z, h2, l2); split_bf16(v.w, h3, l3);
    __nv_bfloat162* ph = (__nv_bfloat162*)GH;
    __nv_bfloat162* pl = (__nv_bfloat162*)GL;
    ph[i * 2]     = __nv_bfloat162(h0, h1);
    ph[i * 2 + 1] = __nv_bfloat162(h2, h3);
    pl[i * 2]     = __nv_bfloat162(l0, l1);
    pl[i * 2 + 1] = __nv_bfloat162(l2, l3);
}

// ---------------- warp-MMA bf16-split GEMM ----------------
// D[m][n] = sum_k A[m][k]*BT[n][k];  CTA 128x128, 8 warps (2x4), warp 64x32.
// KB=512:  A = G split, BT = M1T;  MODE 0: DU = D + DCU
// KB=1024: A = [G|P] split, BT = W2T; MODE 1: out = relu(D+DCZ)+DLFM+g
#define KC     32
#define SP     40                         // smem row stride (bf16 elems): 80B, conflict-free
#define SPLIT_E (128 * SP)                // 5120 elems per split per stage
#define STAGE_E (4 * SPLIT_E)             // Ah|Al|Bh|Bl
#define DYN_BYTES (2 * STAGE_E * 2)       // 81920

template<int KB, int MODE>
__global__ __launch_bounds__(256, 1) void k_mma(const float* __restrict__ G,
                                                float* __restrict__ Out) {
    extern __shared__ __nv_bfloat16 smb[];
    const int tid    = threadIdx.x;
    const int lane   = tid & 31;
    const int wid    = tid >> 5;
    const int gid    = lane >> 2;          // group id 0..7
    const int tig    = lane & 3;           // thread in group
    const int warp_m = wid >> 2;           // 0..1
    const int warp_n = wid & 3;            // 0..3
    const int n0     = blockIdx.x * 128;
    const int row0   = blockIdx.y * 128;
    const int NC     = KB / KC;

    const __nv_bfloat16* BTH = (KB == 512) ? M1TH : W2TH;
    const __nv_bfloat16* BTL = (KB == 512) ? M1TL : W2TL;

    const uint32_t smem0 = (uint32_t)__cvta_generic_to_shared(smb);

    // load one K-chunk: Ah/Al [128 x 32] + Bh/Bl [128 x 32] (16B cp.async x 2048)
    auto load_chunk = [&](int buf, int kk) {
        const uint32_t bb = smem0 + buf * (STAGE_E * 2);
        #pragma unroll
        for (int it = 0; it < 8; ++it) {
            const int q    = tid + it * 256;          // 0..2047
            const int part = q >> 9;                  // 0 Ah, 1 Al, 2 Bh, 3 Bl
            const int idx  = q & 511;
            const int row  = idx >> 2;
            const int seg  = idx & 3;                 // 16B segment (8 elems)
            const uint32_t soff = bb + (uint32_t)(part * SPLIT_E + row * SP + seg * 8) * 2;
            const __nv_bfloat16* gp;
            if (part < 2) {
                int k = kk + seg * 8;
                const __nv_bfloat16* src;
                if (KB == 1024 && k >= 512) { src = (part == 0) ? DPH : DPL; k -= 512; }
                else                        { src = (part == 0) ? GH  : GL; }
                gp = src + (size_t)(row0 + row) * 512 + k;
            } else {
                const __nv_bfloat16* src = (part == 2) ? BTH : BTL;
                gp = src + (size_t)(n0 + row) * KB + kk + seg * 8;
            }
            cpa16(soff, gp);
        }
        cpa_commit();
    };

    float acc[4][4][4];
    #pragma unroll
    for (int i = 0; i < 4; ++i)
        #pragma unroll
        for (int j = 0; j < 4; ++j)
            #pragma unroll
            for (int t = 0; t < 4; ++t) acc[i][j][t] = 0.f;

    load_chunk(0, 0);

    for (int c = 0; c < NC; ++c) {
        if (c + 1 < NC) { load_chunk((c + 1) & 1, (c + 1) * KC); cpa_wait1(); }
        else            { cpa_wait0(); }
        __syncthreads();

        const __nv_bfloat16* st = smb + (c & 1) * STAGE_E;
        const __nv_bfloat16* pAh = st;
        const __nv_bfloat16* pAl = st + SPLIT_E;
        const __nv_bfloat16* pBh = st + 2 * SPLIT_E;
        const __nv_bfloat16* pBl = st + 3 * SPLIT_E;

        #pragma unroll
        for (int ks = 0; ks < 2; ++ks) {
            const int kb = ks * 16;
            uint32_t ah[4][4], bh[4][2], bl[4][2];
            #pragma unroll
            for (int mt = 0; mt < 4; ++mt) {
                const int r = warp_m * 64 + mt * 16 + gid;
                ah[mt][0] = *(const uint32_t*)&pAh[(r)     * SP + kb + tig * 2];
                ah[mt][1] = *(const uint32_t*)&pAh[(r + 8) * SP + kb + tig * 2];
                ah[mt][2] = *(const uint32_t*)&pAh[(r)     * SP + kb + 8 + tig * 2];
                ah[mt][3] = *(const uint32_t*)&pAh[(r + 8) * SP + kb + 8 + tig * 2];
            }
            #pragma unroll
            for (int nt = 0; nt < 4; ++nt) {
                const int nr = warp_n * 32 + nt * 8 + gid;
                bh[nt][0] = *(const uint32_t*)&pBh[nr * SP + kb + tig * 2];
                bh[nt][1] = *(const uint32_t*)&pBh[nr * SP + kb + 8 + tig * 2];
                bl[nt][0] = *(const uint32_t*)&pBl[nr * SP + kb + tig * 2];
                bl[nt][1] = *(const uint32_t*)&pBl[nr * SP + kb + 8 + tig * 2];
            }
            #pragma unroll
            for (int mt = 0; mt < 4; ++mt)
                #pragma unroll
                for (int nt = 0; nt < 4; ++nt) {
                    mma_bf16(acc[mt][nt], ah[mt][0], ah[mt][1], ah[mt][2], ah[mt][3],
                             bh[nt][0], bh[nt][1]);
                    mma_bf16(acc[mt][nt], ah[mt][0], ah[mt][1], ah[mt][2], ah[mt][3],
                             bl[nt][0], bl[nt][1]);
                }
            uint32_t al[4][4];
            #pragma unroll
            for (int mt = 0; mt < 4; ++mt) {
                const int r = warp_m * 64 + mt * 16 + gid;
                al[mt][0] = *(const uint32_t*)&pAl[(r)     * SP + kb + tig * 2];
                al[mt][1] = *(const uint32_t*)&pAl[(r + 8) * SP + kb + tig * 2];
                al[mt][2] = *(const uint32_t*)&pAl[(r)     * SP + kb + 8 + tig * 2];
                al[mt][3] = *(const uint32_t*)&pAl[(r + 8) * SP + kb + 8 + tig * 2];
            }
            #pragma unroll
            for (int mt = 0; mt < 4; ++mt)
                #pragma unroll
                for (int nt = 0; nt < 4; ++nt)
                    mma_bf16(acc[mt][nt], al[mt][0], al[mt][1], al[mt][2], al[mt][3],
                             bh[nt][0], bh[nt][1]);
        }
        __syncthreads();
    }

    // ---- epilogue ----
    #pragma unroll
    for (int mt = 0; mt < 4; ++mt) {
        #pragma unroll
        for (int nt = 0; nt < 4; ++nt) {
            const int col = n0 + warp_n * 32 + nt * 8 + tig * 2;
            #pragma unroll
            for (int half = 0; half < 2; ++half) {
                const int row = row0 + warp_m * 64 + mt * 16 + gid + half * 8;
                const float v0 = acc[mt][nt][half * 2 + 0];
                const float v1 = acc[mt][nt][half * 2 + 1];
                float2 o;
                if (MODE == 0) {
                    o.x = v0 + DCU[col];
                    o.y = v1 + DCU[col + 1];
                    *(float2*)&DU[(size_t)row * 512 + col] = o;
                } else {
                    float2 lm = *(const float2*)&DLFM[(size_t)row * 512 + col];
                    float2 g2 = *(const float2*)&G[(size_t)row * 512 + col];
                    o.x = fmaxf(v0 + DCZ[col],     0.f) + lm.x + g2.x;
                    o.y = fmaxf(v1 + DCZ[col + 1], 0.f) + lm.y + g2.y;
                    *(float2*)&Out[(size_t)row * 512 + col] = o;
                }
            }
        }
    }
}

// ---------------- middle kernel: softmax over 12 local tokens ----------------
__global__ __launch_bounds__(128) void k_mid(const float* __restrict__ lf,
                                             const float* __restrict__ w_dr) {
    __shared__ float sred[4][NLOC];
    __shared__ float swd[NLOC];
    const int b = blockIdx.x, tid = threadIdx.x;
    const int lane = tid & 31, w = tid >> 5;
    if (tid < NLOC) swd[tid] = w_dr[tid];

    float4 u4 = *(const float4*)&DU[(size_t)b * 512 + tid * 4];
    const float* base = lf + (size_t)b * NLOC * 512 + tid * 4;
    float4 lfv[NLOC];
    float part[NLOC];
    #pragma unroll
    for (int k = 0; k < NLOC; ++k) {
        lfv[k] = *(const float4*)&base[k * 512];
        part[k] = lfv[k].x * u4.x + lfv[k].y * u4.y + lfv[k].z * u4.z + lfv[k].w * u4.w;
    }
    #pragma unroll
    for (int k = 0; k < NLOC; ++k) {
        #pragma unroll
        for (int off = 16; off > 0; off >>= 1)
            part[k] += __shfl_xor_sync(0xffffffffu, part[k], off);
    }
    if (lane == 0) {
        #pragma unroll
        for (int k = 0; k < NLOC; ++k) sred[w][k] = part[k];
    }
    __syncthreads();

    float a2[NLOC], mx = -1e30f;
    #pragma unroll
    for (int k = 0; k < NLOC; ++k) {
        float s = (sred[0][k] + sred[1][k] + sred[2][k] + sred[3][k]) * 0.0625f;
        a2[k] = s;
        mx = fmaxf(mx, s);
    }
    float se = 0.f;
    #pragma unroll
    for (int k = 0; k < NLOC; ++k) { a2[k] = expf(a2[k] - mx); se += a2[k]; }
    const float inv = 1.f / se;
    const float bdr = DSWB[1];

    float4 p = {0, 0, 0, 0}, lm = {0, 0, 0, 0};
    #pragma unroll
    for (int k = 0; k < NLOC; ++k) {
        float ak = a2[k] * inv, wk = swd[k];
        p.x = fmaf(ak, lfv[k].x, p.x);  p.y = fmaf(ak, lfv[k].y, p.y);
        p.z = fmaf(ak, lfv[k].z, p.z);  p.w = fmaf(ak, lfv[k].w, p.w);
        lm.x = fmaf(wk, lfv[k].x, lm.x); lm.y = fmaf(wk, lfv[k].y, lm.y);
        lm.z = fmaf(wk, lfv[k].z, lm.z); lm.w = fmaf(wk, lfv[k].w, lm.w);
    }
    lm.x += bdr; lm.y += bdr; lm.z += bdr; lm.w += bdr;
    *(float4*)&DLFM[(size_t)b * 512 + tid * 4] = lm;

    __nv_bfloat16 h0, l0, h1, l1, h2, l2, h3, l3;
    split_bf16(p.x, h0, l0); split_bf16(p.y, h1, l1);
    split_bf16(p.z, h2, l2); split_bf16(p.w, h3, l3);
    __nv_bfloat162* ph = (__nv_bfloat162*)DPH;
    __nv_bfloat162* pl = (__nv_bfloat162*)DPL;
    const size_t i2 = ((size_t)b * 512 + tid * 4) >> 1;
    ph[i2]     = __nv_bfloat162(h0, h1);
    ph[i2 + 1] = __nv_bfloat162(h2, h3);
    pl[i2]     = __nv_bfloat162(l0, l1);
    pl[i2 + 1] = __nv_bfloat162(l2, l3);
}

// ---------------- launch ----------------
extern "C" void kernel_launch(void* const* d_in, const int* in_sizes, int n_in,
                              void* d_out, int out_size) {
    const float* g    = (const float*)d_in[0];
    const float* lf   = (const float*)d_in[1];
    const float* Wq   = (const float*)d_in[2];
    const float* bq   = (const float*)d_in[3];
    const float* Wk   = (const float*)d_in[4];
    // d_in[5] = bk: cancels in the softmax — unused
    const float* Wv   = (const float*)d_in[6];
    const float* bv   = (const float*)d_in[7];
    const float* w_dr = (const float*)d_in[8];
    const float* b_dr = (const float*)d_in[9];
    const float* Wf   = (const float*)d_in[10];
    const float* bf   = (const float*)d_in[11];
    float* out = (float*)d_out;

    cudaFuncSetAttribute(k_mma<512, 0>,  cudaFuncAttributeMaxDynamicSharedMemorySize, DYN_BYTES);
    cudaFuncSetAttribute(k_mma<1024, 1>, cudaFuncAttributeMaxDynamicSharedMemorySize, DYN_BYTES);

    k_sw<<<1, 32>>>(w_dr, b_dr);
    k_prep<<<dim3(8, 8, 3), 256>>>(Wq, Wk, Wv, Wf);
    k_const<<<1, 512>>>(bq, Wk, bv, Wf, bf);
    k_cvt_g<<<B_N * F_D / 1024, 256>>>(g);
    k_mma<512, 0><<<dim3(4, 128), 256, DYN_BYTES>>>(g, nullptr);   // U = g@M1 + c_u
    k_mid<<<B_N, 128>>>(lf, w_dr);                                 // softmax / p / lfm
    k_mma<1024, 1><<<dim3(4, 128), 256, DYN_BYTES>>>(g, out);      // relu([g|p]@W2+cz)+lfm+g
}